// round 15
// baseline (speedup 1.0000x reference)
#include <cuda_runtime.h>
#include <cuda_fp16.h>
#include <math.h>
#include <stdint.h>

constexpr int H    = 128;
constexpr int B    = 512;
constexpr int T    = 128;
constexpr int S    = 1536;   // 3 inputs * B
constexpr int NB2  = 16;     // seqs per lstm block (one mma m-tile)
constexpr int NBLK2= 96;     // S / NB2

constexpr int WST1 = 168;    // lstm1 a-row stride (halves): h 0..127, x 128..143, pad
constexpr int NK1  = 9;
constexpr int WST2 = 136;    // lstm2 a-row stride
constexpr int NK2  = 8;
constexpr int ACT2W = 524;   // act row stride (floats)

// xpre mma smem: W (512 x 136 halves) + x (64 x 136 halves)
constexpr int XSW = 136;
constexpr int XP_W_HALFS = 512 * XSW;
constexpr int XP_SMEM_BYTES = (XP_W_HALFS + 64 * XSW) * 2;
constexpr int NTILE = (S * T) / 64;   // 3072 token tiles

// fp16 packed weights (row-major [gate][k])
__device__ __half g_Whh1_16[512 * 128];
__device__ __half g_Whh2_16[512 * 128];
__device__ __half g_Wih1_16[512 * 16];     // cols 0..4 = Wih1, rest 0
__device__ __half g_W2ih[512 * 128];       // Wih2 fp16 (for xpre)
__device__ float  g_b1[512];
__device__ float  g_b2[512];
__device__ float  g_out1[(size_t)S * T * H];
__device__ float  g_xpre[(size_t)S * T * 512];
__device__ float  g_lasth[S * H];
__device__ float  g_ps1[S * H];
__device__ float  g_pq1[S * H];
__device__ float  g_ps2[S * H];
__device__ float  g_pq2[S * H];
__device__ float2 g_bn1[3 * H];
__device__ float2 g_bn2[3 * H];

__device__ __forceinline__ float sigm(float x) {
    return __fdividef(1.f, 1.f + __expf(-x));
}
__device__ __forceinline__ void mma16816(float& d0, float& d1, float& d2, float& d3,
                                         unsigned a0, unsigned a1, unsigned a2, unsigned a3,
                                         unsigned b0, unsigned b1) {
    asm volatile("mma.sync.aligned.m16n8k16.row.col.f32.f16.f16.f32 "
                 "{%0,%1,%2,%3}, {%4,%5,%6,%7}, {%8,%9}, {%0,%1,%2,%3};"
                 : "+f"(d0), "+f"(d1), "+f"(d2), "+f"(d3)
                 : "r"(a0), "r"(a1), "r"(a2), "r"(a3), "r"(b0), "r"(b1));
}
__device__ __forceinline__ unsigned ldh2(const __half* p) { return *(const unsigned*)p; }

// ---------- pack weights ----------
__global__ void prep_kernel(const float* Wih1, const float* Whh1, const float* bih1, const float* bhh1,
                            const float* Wih2, const float* Whh2, const float* bih2, const float* bhh2) {
    int tid = blockIdx.x * blockDim.x + threadIdx.x;
    int stride = gridDim.x * blockDim.x;
    for (int idx = tid; idx < 512 * 128; idx += stride) {
        g_Whh1_16[idx] = __float2half(Whh1[idx]);
        g_Whh2_16[idx] = __float2half(Whh2[idx]);
        g_W2ih[idx]    = __float2half(Wih2[idx]);
    }
    for (int idx = tid; idx < 512 * 16; idx += stride) {
        int g = idx >> 4, d = idx & 15;
        g_Wih1_16[idx] = __float2half(d < 5 ? Wih1[g * 5 + d] : 0.f);
    }
    for (int j = tid; j < 512; j += stride) {
        g_b1[j] = bih1[j] + bhh1[j];
        g_b2[j] = bih2[j] + bhh2[j];
    }
}

// ---------- layer 1 LSTM via HMMA: weight fragments register-resident ----------
__global__ void __launch_bounds__(512, 1)
lstm1_kernel(const float* __restrict__ xa, const float* __restrict__ xp, const float* __restrict__ xn) {
    __shared__ __align__(16) __half ash[16 * WST1];
    __shared__ __align__(16) float  act[16 * ACT2W];

    const int tid  = threadIdx.x;
    const int w    = tid >> 5;
    const int lane = tid & 31;
    const int r4   = lane >> 2;
    const int c2   = (lane & 3) * 2;
    const int sbase = blockIdx.x * NB2;

    // hoist weight B-fragments: wf[ks][nt][2]
    unsigned wf[NK1][4][2];
#pragma unroll
    for (int nt = 0; nt < 4; nt++) {
        int row = w * 32 + nt * 8 + r4;
#pragma unroll
        for (int ks = 0; ks < NK1; ks++) {
            if (ks < 8) {
                wf[ks][nt][0] = ldh2(g_Whh1_16 + row * 128 + ks * 16 + c2);
                wf[ks][nt][1] = ldh2(g_Whh1_16 + row * 128 + ks * 16 + c2 + 8);
            } else {
                wf[ks][nt][0] = ldh2(g_Wih1_16 + row * 16 + c2);
                wf[ks][nt][1] = ldh2(g_Wih1_16 + row * 16 + c2 + 8);
            }
        }
    }
    float2 bs[4];
#pragma unroll
    for (int nt = 0; nt < 4; nt++) bs[nt] = *(const float2*)&g_b1[w * 32 + nt * 8 + c2];
    const int gt = w >> 2;

    const int m  = tid & 127;
    const int tb = tid >> 7;
    float csr[4] = {0,0,0,0}, sum[4] = {0,0,0,0}, sq[4] = {0,0,0,0};

    const float* xptr = xa; int xoff = 0, xsl = 0, xd = 0;
    const bool is_loader = (tid < NB2 * 5);
    if (is_loader) {
        xsl = tid / 5; xd = tid - 5 * xsl;
        int s = sbase + xsl, in = s >> 9, b = s & 511;
        xptr = (in == 0) ? xa : ((in == 1) ? xp : xn);
        xoff = b * (T * 5) + xd;
    }
    for (int idx = tid; idx < 16 * 21; idx += 512)
        *(uint4*)&ash[(idx / 21) * WST1 + (idx % 21) * 8] = make_uint4(0, 0, 0, 0);
    __syncthreads();
    if (is_loader) ash[xsl * WST1 + 128 + xd] = __float2half(__ldg(&xptr[xoff]));
    __syncthreads();

    for (int t = 0; t < T; t++) {
        float xnv = 0.f;
        if (is_loader && t + 1 < T) xnv = __ldg(&xptr[xoff + (t + 1) * 5]);

        float d[4][4];
#pragma unroll
        for (int nt = 0; nt < 4; nt++)
#pragma unroll
            for (int q = 0; q < 4; q++) d[nt][q] = 0.f;

#pragma unroll
        for (int ks = 0; ks < NK1; ks++) {
            int kb = ks * 16;
            const __half* ab = ash + r4 * WST1 + kb + c2;
            unsigned a0 = ldh2(ab);
            unsigned a1 = ldh2(ab + 8 * WST1);
            unsigned a2 = ldh2(ab + 8);
            unsigned a3 = ldh2(ab + 8 * WST1 + 8);
#pragma unroll
            for (int nt = 0; nt < 4; nt++)
                mma16816(d[nt][0], d[nt][1], d[nt][2], d[nt][3],
                         a0, a1, a2, a3, wf[ks][nt][0], wf[ks][nt][1]);
        }

#pragma unroll
        for (int nt = 0; nt < 4; nt++) {
            float z0 = d[nt][0] + bs[nt].x, z1 = d[nt][1] + bs[nt].y;
            float z2 = d[nt][2] + bs[nt].x, z3 = d[nt][3] + bs[nt].y;
            float a0v, a1v, a2v, a3v;
            if (gt == 2) {
                a0v = fmaf(2.f, sigm(2.f * z0), -1.f);
                a1v = fmaf(2.f, sigm(2.f * z1), -1.f);
                a2v = fmaf(2.f, sigm(2.f * z2), -1.f);
                a3v = fmaf(2.f, sigm(2.f * z3), -1.f);
            } else {
                a0v = sigm(z0); a1v = sigm(z1); a2v = sigm(z2); a3v = sigm(z3);
            }
            int gcol = w * 32 + nt * 8 + c2;
            *(float2*)&act[r4 * ACT2W + gcol]       = make_float2(a0v, a1v);
            *(float2*)&act[(r4 + 8) * ACT2W + gcol] = make_float2(a2v, a3v);
        }
        __syncthreads();

        if (is_loader && t + 1 < T) ash[xsl * WST1 + 128 + xd] = __float2half(xnv);
#pragma unroll
        for (int r = 0; r < 4; r++) {
            int tok = tb + 4 * r;
            const float* arow = act + tok * ACT2W;
            float gi = arow[m], gf = arow[m + 128], gg = arow[m + 256], go = arow[m + 384];
            float c = fmaf(gf, csr[r], gi * gg);
            csr[r] = c;
            float th = fmaf(2.f, sigm(2.f * c), -1.f);
            float h = go * th;
            ash[tok * WST1 + m] = __float2half(h);
            g_out1[((size_t)(sbase + tok) * T + t) * H + m] = h;
            sum[r] += h;
            sq[r] = fmaf(h, h, sq[r]);
        }
        __syncthreads();
    }
#pragma unroll
    for (int r = 0; r < 4; r++) {
        int idx = (sbase + tb + 4 * r) * H + m;
        g_ps1[idx] = sum[r];
        g_pq1[idx] = sq[r];
    }
}

// ---------- BN stats reduce (fp64 tree, deterministic) ----------
__global__ void __launch_bounds__(128)
bn_reduce_kernel(const float* __restrict__ ps, const float* __restrict__ pq,
                 const float* __restrict__ gamma, const float* __restrict__ beta,
                 float2* __restrict__ bnout) {
    __shared__ double rs[128], rq[128];
    int cidx = blockIdx.x;
    int in = cidx >> 7, c = cidx & 127;
    int t = threadIdx.x;
    double s = 0.0, q = 0.0;
    for (int b = t; b < B; b += 128) {
        int idx = (in * B + b) * H + c;
        s += (double)ps[idx];
        q += (double)pq[idx];
    }
    rs[t] = s; rq[t] = q;
    __syncthreads();
    for (int off = 64; off > 0; off >>= 1) {
        if (t < off) { rs[t] += rs[t + off]; rq[t] += rq[t + off]; }
        __syncthreads();
    }
    if (t == 0) {
        double n = (double)B * T;
        double mean = rs[0] / n;
        double var = rq[0] / n - mean * mean;
        float scale = gamma[c] * (float)rsqrt(var + 1e-5);
        float shift = beta[c] - (float)mean * scale;
        bnout[cidx] = make_float2(scale, shift);
    }
}

// ---------- xpre GEMM, persistent blocks: W staged once, loop over token tiles ----------
// output includes +bias (g_b2)
__global__ void __launch_bounds__(512)
xpre_kernel() {
    extern __shared__ __align__(16) __half xsm[];
    __half* Wsh = xsm;                    // [512][XSW]
    __half* xsh = xsm + XP_W_HALFS;       // [64][XSW]

    const int tid  = threadIdx.x;
    const int w    = tid >> 5;
    const int lane = tid & 31;
    const int mt2  = w >> 3;
    const int ng   = w & 7;
    const int r4   = lane >> 2;
    const int c2   = (lane & 3) * 2;

    // stage W once
    for (int idx = tid; idx < 512 * 16; idx += 512) {
        int gate = idx >> 4, c = idx & 15;
        uint4 v = *(const uint4*)(g_W2ih + gate * 128 + c * 8);
        *(uint4*)&Wsh[gate * XSW + c * 8] = v;
    }
    float2 bb2[8];
#pragma unroll
    for (int nt = 0; nt < 8; nt++) bb2[nt] = *(const float2*)&g_b2[ng * 64 + nt * 8 + c2];

    for (int tile = blockIdx.x; tile < NTILE; tile += gridDim.x) {
        const int tok0 = tile * 64;
        __syncthreads();      // protect xsh reuse (also covers W on first pass)
        for (int idx = tid; idx < 2048; idx += 512) {
            int tl = idx >> 5, f4 = idx & 31;
            int tok = tok0 + tl;
            float4 v = __ldg(((const float4*)g_out1) + (size_t)tok * 32 + f4);
            int in = (tok >> 7) >> 9;
            int m0 = f4 * 4;
            float2 b0 = g_bn1[in * H + m0 + 0];
            float2 b1 = g_bn1[in * H + m0 + 1];
            float2 b2 = g_bn1[in * H + m0 + 2];
            float2 b3 = g_bn1[in * H + m0 + 3];
            __half2 h01 = __floats2half2_rn(fmaf(v.x, b0.x, b0.y), fmaf(v.y, b1.x, b1.y));
            __half2 h23 = __floats2half2_rn(fmaf(v.z, b2.x, b2.y), fmaf(v.w, b3.x, b3.y));
            unsigned* dst = (unsigned*)&xsh[tl * XSW + m0];
            dst[0] = *(unsigned*)&h01;
            dst[1] = *(unsigned*)&h23;
        }
        __syncthreads();

        float d[2][8][4];
#pragma unroll
        for (int mi = 0; mi < 2; mi++)
#pragma unroll
            for (int nt = 0; nt < 8; nt++)
#pragma unroll
                for (int q = 0; q < 4; q++) d[mi][nt][q] = 0.f;

#pragma unroll
        for (int ks = 0; ks < 8; ks++) {
            int kb = ks * 16;
            unsigned a[2][4];
#pragma unroll
            for (int mi = 0; mi < 2; mi++) {
                const __half* base = xsh + (mt2 * 32 + mi * 16 + r4) * XSW + kb + c2;
                a[mi][0] = ldh2(base);
                a[mi][1] = ldh2(base + 8 * XSW);
                a[mi][2] = ldh2(base + 8);
                a[mi][3] = ldh2(base + 8 * XSW + 8);
            }
#pragma unroll
            for (int nt = 0; nt < 8; nt++) {
                const __half* bb = Wsh + (ng * 64 + nt * 8 + r4) * XSW + kb + c2;
                unsigned b0 = ldh2(bb);
                unsigned b1 = ldh2(bb + 8);
#pragma unroll
                for (int mi = 0; mi < 2; mi++)
                    mma16816(d[mi][nt][0], d[mi][nt][1], d[mi][nt][2], d[mi][nt][3],
                             a[mi][0], a[mi][1], a[mi][2], a[mi][3], b0, b1);
            }
        }
#pragma unroll
        for (int mi = 0; mi < 2; mi++) {
            int trow = tok0 + mt2 * 32 + mi * 16 + r4;
#pragma unroll
            for (int nt = 0; nt < 8; nt++) {
                int gcol = ng * 64 + nt * 8 + c2;
                *(float2*)&g_xpre[(size_t)trow * 512 + gcol] =
                    make_float2(d[mi][nt][0] + bb2[nt].x, d[mi][nt][1] + bb2[nt].y);
                *(float2*)&g_xpre[(size_t)(trow + 8) * 512 + gcol] =
                    make_float2(d[mi][nt][2] + bb2[nt].x, d[mi][nt][3] + bb2[nt].y);
            }
        }
    }
}

// ---------- layer 2 LSTM via HMMA: weight frags in regs, seed = xpre (bias folded) ----------
__global__ void __launch_bounds__(512, 1)
lstm2_kernel() {
    __shared__ __align__(16) __half ash[16 * WST2];
    __shared__ __align__(16) float  act[16 * ACT2W];

    const int tid  = threadIdx.x;
    const int w    = tid >> 5;
    const int lane = tid & 31;
    const int r4   = lane >> 2;
    const int c2   = (lane & 3) * 2;
    const int sbase = blockIdx.x * NB2;

    unsigned wf[NK2][4][2];
#pragma unroll
    for (int nt = 0; nt < 4; nt++) {
        int row = w * 32 + nt * 8 + r4;
#pragma unroll
        for (int ks = 0; ks < NK2; ks++) {
            wf[ks][nt][0] = ldh2(g_Whh2_16 + row * 128 + ks * 16 + c2);
            wf[ks][nt][1] = ldh2(g_Whh2_16 + row * 128 + ks * 16 + c2 + 8);
        }
    }
    const int gt = w >> 2;

    const int m  = tid & 127;
    const int tb = tid >> 7;
    float csr[4] = {0,0,0,0}, sum[4] = {0,0,0,0}, sq[4] = {0,0,0,0};

    for (int idx = tid; idx < 16 * 17; idx += 512)
        *(uint4*)&ash[(idx / 17) * WST2 + (idx % 17) * 8] = make_uint4(0, 0, 0, 0);
    __syncthreads();

    for (int t = 0; t < T; t++) {
        float2 sd0[4], sd1[4];
        {
            size_t rowA = ((size_t)(sbase + r4) * T + t) * 512;
            size_t rowB = ((size_t)(sbase + r4 + 8) * T + t) * 512;
#pragma unroll
            for (int nt = 0; nt < 4; nt++) {
                int gcol = w * 32 + nt * 8 + c2;
                sd0[nt] = *(const float2*)&g_xpre[rowA + gcol];
                sd1[nt] = *(const float2*)&g_xpre[rowB + gcol];
            }
        }

        float d[4][4];
#pragma unroll
        for (int nt = 0; nt < 4; nt++)
#pragma unroll
            for (int q = 0; q < 4; q++) d[nt][q] = 0.f;

#pragma unroll
        for (int ks = 0; ks < NK2; ks++) {
            int kb = ks * 16;
            const __half* ab = ash + r4 * WST2 + kb + c2;
            unsigned a0 = ldh2(ab);
            unsigned a1 = ldh2(ab + 8 * WST2);
            unsigned a2 = ldh2(ab + 8);
            unsigned a3 = ldh2(ab + 8 * WST2 + 8);
#pragma unroll
            for (int nt = 0; nt < 4; nt++)
                mma16816(d[nt][0], d[nt][1], d[nt][2], d[nt][3],
                         a0, a1, a2, a3, wf[ks][nt][0], wf[ks][nt][1]);
        }

#pragma unroll
        for (int nt = 0; nt < 4; nt++) {
            float z0 = d[nt][0] + sd0[nt].x;
            float z1 = d[nt][1] + sd0[nt].y;
            float z2 = d[nt][2] + sd1[nt].x;
            float z3 = d[nt][3] + sd1[nt].y;
            float a0v, a1v, a2v, a3v;
            if (gt == 2) {
                a0v = fmaf(2.f, sigm(2.f * z0), -1.f);
                a1v = fmaf(2.f, sigm(2.f * z1), -1.f);
                a2v = fmaf(2.f, sigm(2.f * z2), -1.f);
                a3v = fmaf(2.f, sigm(2.f * z3), -1.f);
            } else {
                a0v = sigm(z0); a1v = sigm(z1); a2v = sigm(z2); a3v = sigm(z3);
            }
            int gcol = w * 32 + nt * 8 + c2;
            *(float2*)&act[r4 * ACT2W + gcol]       = make_float2(a0v, a1v);
            *(float2*)&act[(r4 + 8) * ACT2W + gcol] = make_float2(a2v, a3v);
        }
        __syncthreads();

#pragma unroll
        for (int r = 0; r < 4; r++) {
            int tok = tb + 4 * r;
            const float* arow = act + tok * ACT2W;
            float gi = arow[m], gf = arow[m + 128], gg = arow[m + 256], go = arow[m + 384];
            float c = fmaf(gf, csr[r], gi * gg);
            csr[r] = c;
            float th = fmaf(2.f, sigm(2.f * c), -1.f);
            float h = go * th;
            ash[tok * WST2 + m] = __float2half(h);
            sum[r] += h;
            sq[r] = fmaf(h, h, sq[r]);
            if (t == T - 1) g_lasth[(sbase + tok) * H + m] = h;
        }
        __syncthreads();
    }
#pragma unroll
    for (int r = 0; r < 4; r++) {
        int idx = (sbase + tb + 4 * r) * H + m;
        g_ps2[idx] = sum[r];
        g_pq2[idx] = sq[r];
    }
}

// ---------- FC + L2 normalize ----------
__global__ void __launch_bounds__(128)
final_kernel(const float* __restrict__ fcW, const float* __restrict__ fcb, float* __restrict__ out) {
    __shared__ float xn[H];
    __shared__ float emb[H];
    __shared__ float red[128];
    int s = blockIdx.x, j = threadIdx.x;
    int in = s >> 9, b = s & 511;

    float2 bn = g_bn2[in * H + j];
    xn[j] = fmaf(g_lasth[s * H + j], bn.x, bn.y);
    __syncthreads();

    float e = fcb[j];
    const float* wrow = fcW + j * H;
#pragma unroll 4
    for (int k = 0; k < H; k++) e = fmaf(__ldg(&wrow[k]), xn[k], e);
    emb[j] = e;
    red[j] = e * e;
    __syncthreads();
    for (int off = 64; off > 0; off >>= 1) {
        if (j < off) red[j] += red[j + off];
        __syncthreads();
    }
    float norm = sqrtf(red[0]);
    float inv = 1.f / fmaxf(norm, 1e-12f);
    out[((size_t)in * B + b) * H + j] = emb[j] * inv;
}

extern "C" void kernel_launch(void* const* d_in, const int* in_sizes, int n_in,
                              void* d_out, int out_size) {
    const float* a    = (const float*)d_in[0];
    const float* p    = (const float*)d_in[1];
    const float* n    = (const float*)d_in[2];
    const float* Wih1 = (const float*)d_in[3];
    const float* Whh1 = (const float*)d_in[4];
    const float* bih1 = (const float*)d_in[5];
    const float* bhh1 = (const float*)d_in[6];
    const float* g1   = (const float*)d_in[7];
    const float* b1   = (const float*)d_in[8];
    const float* Wih2 = (const float*)d_in[9];
    const float* Whh2 = (const float*)d_in[10];
    const float* bih2 = (const float*)d_in[11];
    const float* bhh2 = (const float*)d_in[12];
    const float* g2   = (const float*)d_in[13];
    const float* b2   = (const float*)d_in[14];
    const float* fcW  = (const float*)d_in[15];
    const float* fcb  = (const float*)d_in[16];
    float* out = (float*)d_out;

    cudaFuncSetAttribute(xpre_kernel, cudaFuncAttributeMaxDynamicSharedMemorySize, XP_SMEM_BYTES);

    float2 *bn1p, *bn2p;
    cudaGetSymbolAddress((void**)&bn1p, g_bn1);
    cudaGetSymbolAddress((void**)&bn2p, g_bn2);
    float *ps1, *pq1, *ps2, *pq2;
    cudaGetSymbolAddress((void**)&ps1, g_ps1);
    cudaGetSymbolAddress((void**)&pq1, g_pq1);
    cudaGetSymbolAddress((void**)&ps2, g_ps2);
    cudaGetSymbolAddress((void**)&pq2, g_pq2);

    prep_kernel<<<128, 256>>>(Wih1, Whh1, bih1, bhh1, Wih2, Whh2, bih2, bhh2);
    lstm1_kernel<<<NBLK2, 512>>>(a, p, n);
    bn_reduce_kernel<<<3 * H, 128>>>(ps1, pq1, g1, b1, bn1p);
    xpre_kernel<<<148, 512, XP_SMEM_BYTES>>>();
    lstm2_kernel<<<NBLK2, 512>>>();
    bn_reduce_kernel<<<3 * H, 128>>>(ps2, pq2, g2, b2, bn2p);
    final_kernel<<<S, 128>>>(fcW, fcb, out);
}

// round 16
// speedup vs baseline: 1.3814x; 1.3814x over previous
#include <cuda_runtime.h>
#include <cuda_fp16.h>
#include <math.h>
#include <stdint.h>

constexpr int H    = 128;
constexpr int B    = 512;
constexpr int T    = 128;
constexpr int S    = 1536;   // 3 inputs * B
constexpr int NB2  = 16;     // seqs per lstm block (one mma m-tile)
constexpr int NBLK2= 96;     // S / NB2

constexpr int WST1 = 168;    // lstm1 a-row stride (halves): h 0..127, x 128..143, pad
constexpr int NK1  = 9;
constexpr int WST2 = 136;    // lstm2 a-row stride
constexpr int NK2  = 8;

// lstm dynamic smem: Wsh + double-buffered ash
constexpr int SMEM1_BYTES = (512 + 32) * WST1 * 2;   // ~178 KB
constexpr int SMEM2_BYTES = (512 + 32) * WST2 * 2;   // ~145 KB

// xpre mma smem: W (512 x 136 halves) + x (64 x 136 halves)
constexpr int XSW = 136;
constexpr int XP_W_HALFS = 512 * XSW;
constexpr int XP_SMEM_BYTES = (XP_W_HALFS + 64 * XSW) * 2;

// fp16 packed weights (row-major [gate][k])
__device__ __half g_Whh1_16[512 * 128];
__device__ __half g_Whh2_16[512 * 128];
__device__ __half g_Wih1_16[512 * 16];     // cols 0..4 = Wih1, rest 0
__device__ __half g_W2ih[512 * 128];       // Wih2 fp16 (for xpre)
__device__ float  g_b1[512];
__device__ float  g_b2[512];
__device__ float  g_out1[(size_t)S * T * H];
__device__ float  g_xpre[(size_t)S * T * 512];
__device__ float  g_lasth[S * H];
__device__ float  g_ps1[S * H];
__device__ float  g_pq1[S * H];
__device__ float  g_ps2[S * H];
__device__ float  g_pq2[S * H];
__device__ float2 g_bn1[3 * H];
__device__ float2 g_bn2[3 * H];

__device__ __forceinline__ float sigm(float x) {
    return __fdividef(1.f, 1.f + __expf(-x));
}
__device__ __forceinline__ void mma16816(float& d0, float& d1, float& d2, float& d3,
                                         unsigned a0, unsigned a1, unsigned a2, unsigned a3,
                                         unsigned b0, unsigned b1) {
    asm volatile("mma.sync.aligned.m16n8k16.row.col.f32.f16.f16.f32 "
                 "{%0,%1,%2,%3}, {%4,%5,%6,%7}, {%8,%9}, {%0,%1,%2,%3};"
                 : "+f"(d0), "+f"(d1), "+f"(d2), "+f"(d3)
                 : "r"(a0), "r"(a1), "r"(a2), "r"(a3), "r"(b0), "r"(b1));
}
__device__ __forceinline__ unsigned ldh2(const __half* p) { return *(const unsigned*)p; }

// ---------- pack weights ----------
__global__ void prep_kernel(const float* Wih1, const float* Whh1, const float* bih1, const float* bhh1,
                            const float* Wih2, const float* Whh2, const float* bih2, const float* bhh2) {
    int tid = blockIdx.x * blockDim.x + threadIdx.x;
    int stride = gridDim.x * blockDim.x;
    for (int idx = tid; idx < 512 * 128; idx += stride) {
        g_Whh1_16[idx] = __float2half(Whh1[idx]);
        g_Whh2_16[idx] = __float2half(Whh2[idx]);
        g_W2ih[idx]    = __float2half(Wih2[idx]);
    }
    for (int idx = tid; idx < 512 * 16; idx += stride) {
        int g = idx >> 4, d = idx & 15;
        g_Wih1_16[idx] = __float2half(d < 5 ? Wih1[g * 5 + d] : 0.f);
    }
    for (int j = tid; j < 512; j += stride) {
        g_b1[j] = bih1[j] + bhh1[j];
        g_b2[j] = bih2[j] + bhh2[j];
    }
}

// ---------- layer 1 LSTM via HMMA: fused register phase-2, double-buffered h ----------
// warp w owns channels w*8..w*8+7; n-tiles at cols {w*8, +128, +256, +384} = i,f,g,o
__global__ void __launch_bounds__(512, 1)
lstm1_kernel(const float* __restrict__ xa, const float* __restrict__ xp, const float* __restrict__ xn) {
    extern __shared__ __align__(16) __half hsm[];
    __half* Wsh  = hsm;                         // [512][WST1]
    __half* ashb = hsm + 512 * WST1;            // two buffers of [16][WST1]

    const int tid  = threadIdx.x;
    const int w    = tid >> 5;
    const int lane = tid & 31;
    const int r4   = lane >> 2;
    const int c2   = (lane & 3) * 2;
    const int sbase = blockIdx.x * NB2;
    const int chw  = w * 8;

    // stage Wsh (946-proven layout): 512 rows x 21 uint4
    for (int idx = tid; idx < 512 * 21; idx += 512) {
        int row = idx / 21, c = idx - row * 21;
        uint4 v = make_uint4(0, 0, 0, 0);
        if (c < 16)       v = *(const uint4*)(g_Whh1_16 + row * 128 + c * 8);
        else if (c < 18)  v = *(const uint4*)(g_Wih1_16 + row * 16 + (c - 16) * 8);
        *(uint4*)&Wsh[row * WST1 + c * 8] = v;
    }
    // zero both ash buffers
    for (int idx = tid; idx < 2 * 16 * 21; idx += 512)
        *(uint4*)&ashb[(idx / 21) * WST1 + (idx % 21) * 8] = make_uint4(0, 0, 0, 0);

    // bias for this thread's gate fragments
    float2 bs[4];
#pragma unroll
    for (int nt = 0; nt < 4; nt++) bs[nt] = *(const float2*)&g_b1[chw + nt * 128 + c2];

    float csr[4] = {0,0,0,0}, sum[4] = {0,0,0,0}, sq[4] = {0,0,0,0};

    const float* xptr = xa; int xoff = 0, xsl = 0, xd = 0;
    const bool is_loader = (tid < NB2 * 5);
    if (is_loader) {
        xsl = tid / 5; xd = tid - 5 * xsl;
        int s = sbase + xsl, in = s >> 9, b = s & 511;
        xptr = (in == 0) ? xa : ((in == 1) ? xp : xn);
        xoff = b * (T * 5) + xd;
    }
    __syncthreads();
    if (is_loader) ashb[xsl * WST1 + 128 + xd] = __float2half(__ldg(&xptr[xoff]));
    __syncthreads();

    for (int t = 0; t < T; t++) {
        __half* cur = ashb + (t & 1) * (16 * WST1);
        __half* nxt = ashb + ((t + 1) & 1) * (16 * WST1);

        float xnv = 0.f;
        if (is_loader && t + 1 < T) xnv = __ldg(&xptr[xoff + (t + 1) * 5]);

        float d[4][4];
#pragma unroll
        for (int nt = 0; nt < 4; nt++)
#pragma unroll
            for (int q = 0; q < 4; q++) d[nt][q] = 0.f;

#pragma unroll
        for (int ks = 0; ks < NK1; ks++) {
            int kb = ks * 16;
            const __half* ab = cur + r4 * WST1 + kb + c2;
            unsigned a0 = ldh2(ab);
            unsigned a1 = ldh2(ab + 8 * WST1);
            unsigned a2 = ldh2(ab + 8);
            unsigned a3 = ldh2(ab + 8 * WST1 + 8);
#pragma unroll
            for (int nt = 0; nt < 4; nt++) {
                const __half* bb = Wsh + (chw + nt * 128 + r4) * WST1 + kb + c2;
                mma16816(d[nt][0], d[nt][1], d[nt][2], d[nt][3],
                         a0, a1, a2, a3, ldh2(bb), ldh2(bb + 8));
            }
        }

        // fused gate/c/h update in registers
        float hq[4];
#pragma unroll
        for (int q = 0; q < 4; q++) {
            float bx = (q & 1) ? 0.f : 0.f;  // (placeholder keeps structure simple)
            float zi = d[0][q] + ((q & 1) ? bs[0].y : bs[0].x);
            float zf = d[1][q] + ((q & 1) ? bs[1].y : bs[1].x);
            float zg = d[2][q] + ((q & 1) ? bs[2].y : bs[2].x);
            float zo = d[3][q] + ((q & 1) ? bs[3].y : bs[3].x);
            (void)bx;
            float gi = sigm(zi);
            float gf = sigm(zf);
            float gg = fmaf(2.f, sigm(2.f * zg), -1.f);
            float go = sigm(zo);
            float c = fmaf(gf, csr[q], gi * gg);
            csr[q] = c;
            float h = go * fmaf(2.f, sigm(2.f * c), -1.f);
            hq[q] = h;
            sum[q] += h;
            sq[q] = fmaf(h, h, sq[q]);
        }
        // write h (fp16) to next buffer + out1 (fp32)
        {
            __half2 h01 = __floats2half2_rn(hq[0], hq[1]);
            __half2 h23 = __floats2half2_rn(hq[2], hq[3]);
            *(unsigned*)&nxt[r4 * WST1 + chw + c2]       = *(unsigned*)&h01;
            *(unsigned*)&nxt[(r4 + 8) * WST1 + chw + c2] = *(unsigned*)&h23;
            *(float2*)&g_out1[((size_t)(sbase + r4) * T + t) * H + chw + c2]       = make_float2(hq[0], hq[1]);
            *(float2*)&g_out1[((size_t)(sbase + r4 + 8) * T + t) * H + chw + c2]   = make_float2(hq[2], hq[3]);
        }
        if (is_loader && t + 1 < T) nxt[xsl * WST1 + 128 + xd] = __float2half(xnv);
        __syncthreads();
    }
    *(float2*)&g_ps1[(sbase + r4) * H + chw + c2]     = make_float2(sum[0], sum[1]);
    *(float2*)&g_ps1[(sbase + r4 + 8) * H + chw + c2] = make_float2(sum[2], sum[3]);
    *(float2*)&g_pq1[(sbase + r4) * H + chw + c2]     = make_float2(sq[0], sq[1]);
    *(float2*)&g_pq1[(sbase + r4 + 8) * H + chw + c2] = make_float2(sq[2], sq[3]);
}

// ---------- BN stats reduce (fp64 tree, deterministic) ----------
__global__ void __launch_bounds__(128)
bn_reduce_kernel(const float* __restrict__ ps, const float* __restrict__ pq,
                 const float* __restrict__ gamma, const float* __restrict__ beta,
                 float2* __restrict__ bnout) {
    __shared__ double rs[128], rq[128];
    int cidx = blockIdx.x;
    int in = cidx >> 7, c = cidx & 127;
    int t = threadIdx.x;
    double s = 0.0, q = 0.0;
    for (int b = t; b < B; b += 128) {
        int idx = (in * B + b) * H + c;
        s += (double)ps[idx];
        q += (double)pq[idx];
    }
    rs[t] = s; rq[t] = q;
    __syncthreads();
    for (int off = 64; off > 0; off >>= 1) {
        if (t < off) { rs[t] += rs[t + off]; rq[t] += rq[t + off]; }
        __syncthreads();
    }
    if (t == 0) {
        double n = (double)B * T;
        double mean = rs[0] / n;
        double var = rq[0] / n - mean * mean;
        float scale = gamma[c] * (float)rsqrt(var + 1e-5);
        float shift = beta[c] - (float)mean * scale;
        bnout[cidx] = make_float2(scale, shift);
    }
}

// ---------- xpre GEMM via HMMA (946-proven): 64 tokens x 512 gates per block ----------
__global__ void __launch_bounds__(512)
xpre_kernel() {
    extern __shared__ __align__(16) __half xsm[];
    __half* Wsh = xsm;                    // [512][XSW]
    __half* xsh = xsm + XP_W_HALFS;       // [64][XSW]

    const int tid  = threadIdx.x;
    const int tok0 = blockIdx.x * 64;

    for (int idx = tid; idx < 512 * 16; idx += 512) {
        int gate = idx >> 4, c = idx & 15;
        uint4 v = *(const uint4*)(g_W2ih + gate * 128 + c * 8);
        *(uint4*)&Wsh[gate * XSW + c * 8] = v;
    }
    for (int idx = tid; idx < 2048; idx += 512) {
        int tl = idx >> 5, f4 = idx & 31;
        int tok = tok0 + tl;
        float4 v = __ldg(((const float4*)g_out1) + (size_t)tok * 32 + f4);
        int in = (tok >> 7) >> 9;
        int m0 = f4 * 4;
        float2 b0 = g_bn1[in * H + m0 + 0];
        float2 b1 = g_bn1[in * H + m0 + 1];
        float2 b2 = g_bn1[in * H + m0 + 2];
        float2 b3 = g_bn1[in * H + m0 + 3];
        __half2 h01 = __floats2half2_rn(fmaf(v.x, b0.x, b0.y), fmaf(v.y, b1.x, b1.y));
        __half2 h23 = __floats2half2_rn(fmaf(v.z, b2.x, b2.y), fmaf(v.w, b3.x, b3.y));
        unsigned* dst = (unsigned*)&xsh[tl * XSW + m0];
        dst[0] = *(unsigned*)&h01;
        dst[1] = *(unsigned*)&h23;
    }
    __syncthreads();

    const int w    = tid >> 5;
    const int lane = tid & 31;
    const int mt2  = w >> 3;
    const int ng   = w & 7;
    const int r4   = lane >> 2;
    const int c2   = (lane & 3) * 2;

    float d[2][8][4];
#pragma unroll
    for (int mi = 0; mi < 2; mi++)
#pragma unroll
        for (int nt = 0; nt < 8; nt++)
#pragma unroll
            for (int q = 0; q < 4; q++) d[mi][nt][q] = 0.f;

#pragma unroll
    for (int ks = 0; ks < 8; ks++) {
        int kb = ks * 16;
        unsigned a[2][4];
#pragma unroll
        for (int mi = 0; mi < 2; mi++) {
            const __half* base = xsh + (mt2 * 32 + mi * 16 + r4) * XSW + kb + c2;
            a[mi][0] = ldh2(base);
            a[mi][1] = ldh2(base + 8 * XSW);
            a[mi][2] = ldh2(base + 8);
            a[mi][3] = ldh2(base + 8 * XSW + 8);
        }
#pragma unroll
        for (int nt = 0; nt < 8; nt++) {
            const __half* bb = Wsh + (ng * 64 + nt * 8 + r4) * XSW + kb + c2;
            unsigned b0 = ldh2(bb);
            unsigned b1 = ldh2(bb + 8);
#pragma unroll
            for (int mi = 0; mi < 2; mi++)
                mma16816(d[mi][nt][0], d[mi][nt][1], d[mi][nt][2], d[mi][nt][3],
                         a[mi][0], a[mi][1], a[mi][2], a[mi][3], b0, b1);
        }
    }
#pragma unroll
    for (int mi = 0; mi < 2; mi++) {
        int trow = tok0 + mt2 * 32 + mi * 16 + r4;
#pragma unroll
        for (int nt = 0; nt < 8; nt++) {
            int gcol = ng * 64 + nt * 8 + c2;
            *(float2*)&g_xpre[(size_t)trow * 512 + gcol]       = make_float2(d[mi][nt][0], d[mi][nt][1]);
            *(float2*)&g_xpre[(size_t)(trow + 8) * 512 + gcol] = make_float2(d[mi][nt][2], d[mi][nt][3]);
        }
    }
}

// ---------- layer 2 LSTM via HMMA: fused register phase-2, double-buffered h ----------
__global__ void __launch_bounds__(512, 1)
lstm2_kernel() {
    extern __shared__ __align__(16) __half hsm[];
    __half* Wsh  = hsm;                         // [512][WST2]
    __half* ashb = hsm + 512 * WST2;            // two buffers of [16][WST2]

    const int tid  = threadIdx.x;
    const int w    = tid >> 5;
    const int lane = tid & 31;
    const int r4   = lane >> 2;
    const int c2   = (lane & 3) * 2;
    const int sbase = blockIdx.x * NB2;
    const int chw  = w * 8;

    for (int idx = tid; idx < 512 * 17; idx += 512) {
        int row = idx / 17, c = idx - row * 17;
        uint4 v = make_uint4(0, 0, 0, 0);
        if (c < 16) v = *(const uint4*)(g_Whh2_16 + row * 128 + c * 8);
        *(uint4*)&Wsh[row * WST2 + c * 8] = v;
    }
    for (int idx = tid; idx < 2 * 16 * 17; idx += 512)
        *(uint4*)&ashb[(idx / 17) * WST2 + (idx % 17) * 8] = make_uint4(0, 0, 0, 0);

    float2 bs[4];
#pragma unroll
    for (int nt = 0; nt < 4; nt++) bs[nt] = *(const float2*)&g_b2[chw + nt * 128 + c2];

    float csr[4] = {0,0,0,0}, sum[4] = {0,0,0,0}, sq[4] = {0,0,0,0};
    __syncthreads();

    for (int t = 0; t < T; t++) {
        __half* cur = ashb + (t & 1) * (16 * WST2);
        __half* nxt = ashb + ((t + 1) & 1) * (16 * WST2);

        // seeds for this thread's fragments (latency hidden under mma)
        float2 sd0[4], sd1[4];
        {
            size_t rowA = ((size_t)(sbase + r4) * T + t) * 512;
            size_t rowB = ((size_t)(sbase + r4 + 8) * T + t) * 512;
#pragma unroll
            for (int nt = 0; nt < 4; nt++) {
                int gcol = chw + nt * 128 + c2;
                sd0[nt] = *(const float2*)&g_xpre[rowA + gcol];
                sd1[nt] = *(const float2*)&g_xpre[rowB + gcol];
            }
        }

        float d[4][4];
#pragma unroll
        for (int nt = 0; nt < 4; nt++)
#pragma unroll
            for (int q = 0; q < 4; q++) d[nt][q] = 0.f;

#pragma unroll
        for (int ks = 0; ks < NK2; ks++) {
            int kb = ks * 16;
            const __half* ab = cur + r4 * WST2 + kb + c2;
            unsigned a0 = ldh2(ab);
            unsigned a1 = ldh2(ab + 8 * WST2);
            unsigned a2 = ldh2(ab + 8);
            unsigned a3 = ldh2(ab + 8 * WST2 + 8);
#pragma unroll
            for (int nt = 0; nt < 4; nt++) {
                const __half* bb = Wsh + (chw + nt * 128 + r4) * WST2 + kb + c2;
                mma16816(d[nt][0], d[nt][1], d[nt][2], d[nt][3],
                         a0, a1, a2, a3, ldh2(bb), ldh2(bb + 8));
            }
        }

        float hq[4];
#pragma unroll
        for (int q = 0; q < 4; q++) {
            float si = (q < 2) ? ((q & 1) ? sd0[0].y : sd0[0].x) : ((q & 1) ? sd1[0].y : sd1[0].x);
            float sf = (q < 2) ? ((q & 1) ? sd0[1].y : sd0[1].x) : ((q & 1) ? sd1[1].y : sd1[1].x);
            float sg = (q < 2) ? ((q & 1) ? sd0[2].y : sd0[2].x) : ((q & 1) ? sd1[2].y : sd1[2].x);
            float so = (q < 2) ? ((q & 1) ? sd0[3].y : sd0[3].x) : ((q & 1) ? sd1[3].y : sd1[3].x);
            float zi = d[0][q] + ((q & 1) ? bs[0].y : bs[0].x) + si;
            float zf = d[1][q] + ((q & 1) ? bs[1].y : bs[1].x) + sf;
            float zg = d[2][q] + ((q & 1) ? bs[2].y : bs[2].x) + sg;
            float zo = d[3][q] + ((q & 1) ? bs[3].y : bs[3].x) + so;
            float gi = sigm(zi);
            float gf = sigm(zf);
            float gg = fmaf(2.f, sigm(2.f * zg), -1.f);
            float go = sigm(zo);
            float c = fmaf(gf, csr[q], gi * gg);
            csr[q] = c;
            float h = go * fmaf(2.f, sigm(2.f * c), -1.f);
            hq[q] = h;
            sum[q] += h;
            sq[q] = fmaf(h, h, sq[q]);
        }
        {
            __half2 h01 = __floats2half2_rn(hq[0], hq[1]);
            __half2 h23 = __floats2half2_rn(hq[2], hq[3]);
            *(unsigned*)&nxt[r4 * WST2 + chw + c2]       = *(unsigned*)&h01;
            *(unsigned*)&nxt[(r4 + 8) * WST2 + chw + c2] = *(unsigned*)&h23;
        }
        if (t == T - 1) {
            *(float2*)&g_lasth[(sbase + r4) * H + chw + c2]     = make_float2(hq[0], hq[1]);
            *(float2*)&g_lasth[(sbase + r4 + 8) * H + chw + c2] = make_float2(hq[2], hq[3]);
        }
        __syncthreads();
    }
    *(float2*)&g_ps2[(sbase + r4) * H + chw + c2]     = make_float2(sum[0], sum[1]);
    *(float2*)&g_ps2[(sbase + r4 + 8) * H + chw + c2] = make_float2(sum[2], sum[3]);
    *(float2*)&g_pq2[(sbase + r4) * H + chw + c2]     = make_float2(sq[0], sq[1]);
    *(float2*)&g_pq2[(sbase + r4 + 8) * H + chw + c2] = make_float2(sq[2], sq[3]);
}

// ---------- FC + L2 normalize ----------
__global__ void __launch_bounds__(128)
final_kernel(const float* __restrict__ fcW, const float* __restrict__ fcb, float* __restrict__ out) {
    __shared__ float xn[H];
    __shared__ float emb[H];
    __shared__ float red[128];
    int s = blockIdx.x, j = threadIdx.x;
    int in = s >> 9, b = s & 511;

    float2 bn = g_bn2[in * H + j];
    xn[j] = fmaf(g_lasth[s * H + j], bn.x, bn.y);
    __syncthreads();

    float e = fcb[j];
    const float* wrow = fcW + j * H;
#pragma unroll 4
    for (int k = 0; k < H; k++) e = fmaf(__ldg(&wrow[k]), xn[k], e);
    emb[j] = e;
    red[j] = e * e;
    __syncthreads();
    for (int off = 64; off > 0; off >>= 1) {
        if (j < off) red[j] += red[j + off];
        __syncthreads();
    }
    float norm = sqrtf(red[0]);
    float inv = 1.f / fmaxf(norm, 1e-12f);
    out[((size_t)in * B + b) * H + j] = emb[j] * inv;
}

extern "C" void kernel_launch(void* const* d_in, const int* in_sizes, int n_in,
                              void* d_out, int out_size) {
    const float* a    = (const float*)d_in[0];
    const float* p    = (const float*)d_in[1];
    const float* n    = (const float*)d_in[2];
    const float* Wih1 = (const float*)d_in[3];
    const float* Whh1 = (const float*)d_in[4];
    const float* bih1 = (const float*)d_in[5];
    const float* bhh1 = (const float*)d_in[6];
    const float* g1   = (const float*)d_in[7];
    const float* b1   = (const float*)d_in[8];
    const float* Wih2 = (const float*)d_in[9];
    const float* Whh2 = (const float*)d_in[10];
    const float* bih2 = (const float*)d_in[11];
    const float* bhh2 = (const float*)d_in[12];
    const float* g2   = (const float*)d_in[13];
    const float* b2   = (const float*)d_in[14];
    const float* fcW  = (const float*)d_in[15];
    const float* fcb  = (const float*)d_in[16];
    float* out = (float*)d_out;

    cudaFuncSetAttribute(lstm1_kernel, cudaFuncAttributeMaxDynamicSharedMemorySize, SMEM1_BYTES);
    cudaFuncSetAttribute(lstm2_kernel, cudaFuncAttributeMaxDynamicSharedMemorySize, SMEM2_BYTES);
    cudaFuncSetAttribute(xpre_kernel,  cudaFuncAttributeMaxDynamicSharedMemorySize, XP_SMEM_BYTES);

    float2 *bn1p, *bn2p;
    cudaGetSymbolAddress((void**)&bn1p, g_bn1);
    cudaGetSymbolAddress((void**)&bn2p, g_bn2);
    float *ps1, *pq1, *ps2, *pq2;
    cudaGetSymbolAddress((void**)&ps1, g_ps1);
    cudaGetSymbolAddress((void**)&pq1, g_pq1);
    cudaGetSymbolAddress((void**)&ps2, g_ps2);
    cudaGetSymbolAddress((void**)&pq2, g_pq2);

    prep_kernel<<<128, 256>>>(Wih1, Whh1, bih1, bhh1, Wih2, Whh2, bih2, bhh2);
    lstm1_kernel<<<NBLK2, 512, SMEM1_BYTES>>>(a, p, n);
    bn_reduce_kernel<<<3 * H, 128>>>(ps1, pq1, g1, b1, bn1p);
    xpre_kernel<<<(S * T) / 64, 512, XP_SMEM_BYTES>>>();
    lstm2_kernel<<<NBLK2, 512, SMEM2_BYTES>>>();
    bn_reduce_kernel<<<3 * H, 128>>>(ps2, pq2, g2, b2, bn2p);
    final_kernel<<<S, 128>>>(fcW, fcb, out);
}

// round 17
// speedup vs baseline: 1.4309x; 1.0358x over previous
#include <cuda_runtime.h>
#include <cuda_fp16.h>
#include <math.h>
#include <stdint.h>

constexpr int H    = 128;
constexpr int B    = 512;
constexpr int T    = 128;
constexpr int S    = 1536;   // 3 inputs * B
constexpr int NB2  = 16;     // seqs per lstm block (one mma m-tile)
constexpr int NBLK2= 96;     // S / NB2

constexpr int WST1 = 168;    // lstm1 a-row stride (halves): h 0..127, x 128..143, pad
constexpr int NK1  = 9;
constexpr int WST2 = 136;    // lstm2 a-row stride
constexpr int NK2  = 8;

// lstm dynamic smem: Wsh + double-buffered ash
constexpr int SMEM1_BYTES = (512 + 32) * WST1 * 2;   // ~178 KB
constexpr int SMEM2_BYTES = (512 + 32) * WST2 * 2;   // ~145 KB

// xpre mma smem: W (512 x 136 halves) + x (64 x 136 halves)
constexpr int XSW = 136;
constexpr int XP_W_HALFS = 512 * XSW;
constexpr int XP_SMEM_BYTES = (XP_W_HALFS + 64 * XSW) * 2;

// fp16 packed weights (row-major [gate][k])
__device__ __half g_Whh1_16[512 * 128];
__device__ __half g_Whh2_16[512 * 128];
__device__ __half g_Wih1_16[512 * 16];     // cols 0..4 = Wih1, rest 0
__device__ __half g_W2ih[512 * 128];       // Wih2 fp16 (for xpre)
__device__ float  g_b1[512];
__device__ float  g_b2[512];
__device__ __half g_out1[(size_t)S * T * H];        // fp16 layer-1 output (50 MB)
__device__ __half g_xpre[(size_t)S * T * 512];      // fp16 seeds (200 MB)
__device__ float  g_lasth[S * H];
__device__ float  g_ps1[S * H];
__device__ float  g_pq1[S * H];
__device__ float  g_ps2[S * H];
__device__ float  g_pq2[S * H];
__device__ float2 g_bn1[3 * H];
__device__ float2 g_bn2[3 * H];

__device__ __forceinline__ float sigm(float x) {
    return __fdividef(1.f, 1.f + __expf(-x));
}
__device__ __forceinline__ void mma16816(float& d0, float& d1, float& d2, float& d3,
                                         unsigned a0, unsigned a1, unsigned a2, unsigned a3,
                                         unsigned b0, unsigned b1) {
    asm volatile("mma.sync.aligned.m16n8k16.row.col.f32.f16.f16.f32 "
                 "{%0,%1,%2,%3}, {%4,%5,%6,%7}, {%8,%9}, {%0,%1,%2,%3};"
                 : "+f"(d0), "+f"(d1), "+f"(d2), "+f"(d3)
                 : "r"(a0), "r"(a1), "r"(a2), "r"(a3), "r"(b0), "r"(b1));
}
__device__ __forceinline__ unsigned ldh2(const __half* p) { return *(const unsigned*)p; }

// ---------- pack weights ----------
__global__ void prep_kernel(const float* Wih1, const float* Whh1, const float* bih1, const float* bhh1,
                            const float* Wih2, const float* Whh2, const float* bih2, const float* bhh2) {
    int tid = blockIdx.x * blockDim.x + threadIdx.x;
    int stride = gridDim.x * blockDim.x;
    for (int idx = tid; idx < 512 * 128; idx += stride) {
        g_Whh1_16[idx] = __float2half(Whh1[idx]);
        g_Whh2_16[idx] = __float2half(Whh2[idx]);
        g_W2ih[idx]    = __float2half(Wih2[idx]);
    }
    for (int idx = tid; idx < 512 * 16; idx += stride) {
        int g = idx >> 4, d = idx & 15;
        g_Wih1_16[idx] = __float2half(d < 5 ? Wih1[g * 5 + d] : 0.f);
    }
    for (int j = tid; j < 512; j += stride) {
        g_b1[j] = bih1[j] + bhh1[j];
        g_b2[j] = bih2[j] + bhh2[j];
    }
}

// ---------- layer 1 LSTM via HMMA: fused register phase-2, double-buffered h ----------
__global__ void __launch_bounds__(512, 1)
lstm1_kernel(const float* __restrict__ xa, const float* __restrict__ xp, const float* __restrict__ xn) {
    extern __shared__ __align__(16) __half hsm[];
    __half* Wsh  = hsm;                         // [512][WST1]
    __half* ashb = hsm + 512 * WST1;            // two buffers of [16][WST1]

    const int tid  = threadIdx.x;
    const int w    = tid >> 5;
    const int lane = tid & 31;
    const int r4   = lane >> 2;
    const int c2   = (lane & 3) * 2;
    const int sbase = blockIdx.x * NB2;
    const int chw  = w * 8;

    for (int idx = tid; idx < 512 * 21; idx += 512) {
        int row = idx / 21, c = idx - row * 21;
        uint4 v = make_uint4(0, 0, 0, 0);
        if (c < 16)       v = *(const uint4*)(g_Whh1_16 + row * 128 + c * 8);
        else if (c < 18)  v = *(const uint4*)(g_Wih1_16 + row * 16 + (c - 16) * 8);
        *(uint4*)&Wsh[row * WST1 + c * 8] = v;
    }
    for (int idx = tid; idx < 2 * 16 * 21; idx += 512)
        *(uint4*)&ashb[(idx / 21) * WST1 + (idx % 21) * 8] = make_uint4(0, 0, 0, 0);

    float2 bs[4];
#pragma unroll
    for (int nt = 0; nt < 4; nt++) bs[nt] = *(const float2*)&g_b1[chw + nt * 128 + c2];

    float csr[4] = {0,0,0,0}, sum[4] = {0,0,0,0}, sq[4] = {0,0,0,0};

    const float* xptr = xa; int xoff = 0, xsl = 0, xd = 0;
    const bool is_loader = (tid < NB2 * 5);
    if (is_loader) {
        xsl = tid / 5; xd = tid - 5 * xsl;
        int s = sbase + xsl, in = s >> 9, b = s & 511;
        xptr = (in == 0) ? xa : ((in == 1) ? xp : xn);
        xoff = b * (T * 5) + xd;
    }
    __syncthreads();
    if (is_loader) ashb[xsl * WST1 + 128 + xd] = __float2half(__ldg(&xptr[xoff]));
    __syncthreads();

    for (int t = 0; t < T; t++) {
        __half* cur = ashb + (t & 1) * (16 * WST1);
        __half* nxt = ashb + ((t + 1) & 1) * (16 * WST1);

        float xnv = 0.f;
        if (is_loader && t + 1 < T) xnv = __ldg(&xptr[xoff + (t + 1) * 5]);

        float d[4][4];
#pragma unroll
        for (int nt = 0; nt < 4; nt++)
#pragma unroll
            for (int q = 0; q < 4; q++) d[nt][q] = 0.f;

#pragma unroll
        for (int ks = 0; ks < NK1; ks++) {
            int kb = ks * 16;
            const __half* ab = cur + r4 * WST1 + kb + c2;
            unsigned a0 = ldh2(ab);
            unsigned a1 = ldh2(ab + 8 * WST1);
            unsigned a2 = ldh2(ab + 8);
            unsigned a3 = ldh2(ab + 8 * WST1 + 8);
#pragma unroll
            for (int nt = 0; nt < 4; nt++) {
                const __half* bb = Wsh + (chw + nt * 128 + r4) * WST1 + kb + c2;
                mma16816(d[nt][0], d[nt][1], d[nt][2], d[nt][3],
                         a0, a1, a2, a3, ldh2(bb), ldh2(bb + 8));
            }
        }

        float hq[4];
#pragma unroll
        for (int q = 0; q < 4; q++) {
            float zi = d[0][q] + ((q & 1) ? bs[0].y : bs[0].x);
            float zf = d[1][q] + ((q & 1) ? bs[1].y : bs[1].x);
            float zg = d[2][q] + ((q & 1) ? bs[2].y : bs[2].x);
            float zo = d[3][q] + ((q & 1) ? bs[3].y : bs[3].x);
            float gi = sigm(zi);
            float gf = sigm(zf);
            float gg = fmaf(2.f, sigm(2.f * zg), -1.f);
            float go = sigm(zo);
            float c = fmaf(gf, csr[q], gi * gg);
            csr[q] = c;
            float h = go * fmaf(2.f, sigm(2.f * c), -1.f);
            hq[q] = h;
            sum[q] += h;
            sq[q] = fmaf(h, h, sq[q]);
        }
        {
            __half2 h01 = __floats2half2_rn(hq[0], hq[1]);
            __half2 h23 = __floats2half2_rn(hq[2], hq[3]);
            *(unsigned*)&nxt[r4 * WST1 + chw + c2]       = *(unsigned*)&h01;
            *(unsigned*)&nxt[(r4 + 8) * WST1 + chw + c2] = *(unsigned*)&h23;
            // fp16 out1 store (same precision as recurrent h)
            *(unsigned*)&g_out1[((size_t)(sbase + r4) * T + t) * H + chw + c2]     = *(unsigned*)&h01;
            *(unsigned*)&g_out1[((size_t)(sbase + r4 + 8) * T + t) * H + chw + c2] = *(unsigned*)&h23;
        }
        if (is_loader && t + 1 < T) nxt[xsl * WST1 + 128 + xd] = __float2half(xnv);
        __syncthreads();
    }
    *(float2*)&g_ps1[(sbase + r4) * H + chw + c2]     = make_float2(sum[0], sum[1]);
    *(float2*)&g_ps1[(sbase + r4 + 8) * H + chw + c2] = make_float2(sum[2], sum[3]);
    *(float2*)&g_pq1[(sbase + r4) * H + chw + c2]     = make_float2(sq[0], sq[1]);
    *(float2*)&g_pq1[(sbase + r4 + 8) * H + chw + c2] = make_float2(sq[2], sq[3]);
}

// ---------- BN stats reduce (fp64 tree, deterministic) ----------
__global__ void __launch_bounds__(128)
bn_reduce_kernel(const float* __restrict__ ps, const float* __restrict__ pq,
                 const float* __restrict__ gamma, const float* __restrict__ beta,
                 float2* __restrict__ bnout) {
    __shared__ double rs[128], rq[128];
    int cidx = blockIdx.x;
    int in = cidx >> 7, c = cidx & 127;
    int t = threadIdx.x;
    double s = 0.0, q = 0.0;
    for (int b = t; b < B; b += 128) {
        int idx = (in * B + b) * H + c;
        s += (double)ps[idx];
        q += (double)pq[idx];
    }
    rs[t] = s; rq[t] = q;
    __syncthreads();
    for (int off = 64; off > 0; off >>= 1) {
        if (t < off) { rs[t] += rs[t + off]; rq[t] += rq[t + off]; }
        __syncthreads();
    }
    if (t == 0) {
        double n = (double)B * T;
        double mean = rs[0] / n;
        double var = rq[0] / n - mean * mean;
        float scale = gamma[c] * (float)rsqrt(var + 1e-5);
        float shift = beta[c] - (float)mean * scale;
        bnout[cidx] = make_float2(scale, shift);
    }
}

// ---------- xpre GEMM via HMMA: 2 token tiles (128 tokens) per block ----------
__global__ void __launch_bounds__(512)
xpre_kernel() {
    extern __shared__ __align__(16) __half xsm[];
    __half* Wsh = xsm;                    // [512][XSW]
    __half* xsh = xsm + XP_W_HALFS;       // [64][XSW]

    const int tid  = threadIdx.x;
    const int w    = tid >> 5;
    const int lane = tid & 31;
    const int mt2  = w >> 3;
    const int ng   = w & 7;
    const int r4   = lane >> 2;
    const int c2   = (lane & 3) * 2;

    // stage W once
    for (int idx = tid; idx < 512 * 16; idx += 512) {
        int gate = idx >> 4, c = idx & 15;
        uint4 v = *(const uint4*)(g_W2ih + gate * 128 + c * 8);
        *(uint4*)&Wsh[gate * XSW + c * 8] = v;
    }

#pragma unroll
    for (int sub = 0; sub < 2; sub++) {
        const int tok0 = (blockIdx.x * 2 + sub) * 64;
        __syncthreads();   // W ready (first pass) / xsh readers done (second pass)
        // stage x tile from fp16 out1, BN1-normalize
        for (int idx = tid; idx < 1024; idx += 512) {
            int tl = idx >> 4, u4 = idx & 15;
            int tok = tok0 + tl;
            uint4 v = *(const uint4*)(g_out1 + (size_t)tok * H + u4 * 8);
            int in = (tok >> 7) >> 9;
            int m0 = u4 * 8;
            unsigned* dst = (unsigned*)&xsh[tl * XSW + m0];
            unsigned* src = (unsigned*)&v;
#pragma unroll
            for (int j = 0; j < 4; j++) {
                float2 hv = __half22float2(*(__half2*)&src[j]);
                float2 bA = g_bn1[in * H + m0 + 2 * j];
                float2 bBv = g_bn1[in * H + m0 + 2 * j + 1];
                __half2 o = __floats2half2_rn(fmaf(hv.x, bA.x, bA.y), fmaf(hv.y, bBv.x, bBv.y));
                dst[j] = *(unsigned*)&o;
            }
        }
        __syncthreads();

        float d[2][8][4];
#pragma unroll
        for (int mi = 0; mi < 2; mi++)
#pragma unroll
            for (int nt = 0; nt < 8; nt++)
#pragma unroll
                for (int q = 0; q < 4; q++) d[mi][nt][q] = 0.f;

#pragma unroll
        for (int ks = 0; ks < 8; ks++) {
            int kb = ks * 16;
            unsigned a[2][4];
#pragma unroll
            for (int mi = 0; mi < 2; mi++) {
                const __half* base = xsh + (mt2 * 32 + mi * 16 + r4) * XSW + kb + c2;
                a[mi][0] = ldh2(base);
                a[mi][1] = ldh2(base + 8 * XSW);
                a[mi][2] = ldh2(base + 8);
                a[mi][3] = ldh2(base + 8 * XSW + 8);
            }
#pragma unroll
            for (int nt = 0; nt < 8; nt++) {
                const __half* bb = Wsh + (ng * 64 + nt * 8 + r4) * XSW + kb + c2;
                unsigned b0 = ldh2(bb);
                unsigned b1 = ldh2(bb + 8);
#pragma unroll
                for (int mi = 0; mi < 2; mi++)
                    mma16816(d[mi][nt][0], d[mi][nt][1], d[mi][nt][2], d[mi][nt][3],
                             a[mi][0], a[mi][1], a[mi][2], a[mi][3], b0, b1);
            }
        }
#pragma unroll
        for (int mi = 0; mi < 2; mi++) {
            int trow = tok0 + mt2 * 32 + mi * 16 + r4;
#pragma unroll
            for (int nt = 0; nt < 8; nt++) {
                int gcol = ng * 64 + nt * 8 + c2;
                __half2 o0 = __floats2half2_rn(d[mi][nt][0], d[mi][nt][1]);
                __half2 o1 = __floats2half2_rn(d[mi][nt][2], d[mi][nt][3]);
                *(unsigned*)&g_xpre[(size_t)trow * 512 + gcol]       = *(unsigned*)&o0;
                *(unsigned*)&g_xpre[(size_t)(trow + 8) * 512 + gcol] = *(unsigned*)&o1;
            }
        }
    }
}

// ---------- layer 2 LSTM via HMMA: fused register phase-2, double-buffered h ----------
__global__ void __launch_bounds__(512, 1)
lstm2_kernel() {
    extern __shared__ __align__(16) __half hsm[];
    __half* Wsh  = hsm;                         // [512][WST2]
    __half* ashb = hsm + 512 * WST2;            // two buffers of [16][WST2]

    const int tid  = threadIdx.x;
    const int w    = tid >> 5;
    const int lane = tid & 31;
    const int r4   = lane >> 2;
    const int c2   = (lane & 3) * 2;
    const int sbase = blockIdx.x * NB2;
    const int chw  = w * 8;

    for (int idx = tid; idx < 512 * 17; idx += 512) {
        int row = idx / 17, c = idx - row * 17;
        uint4 v = make_uint4(0, 0, 0, 0);
        if (c < 16) v = *(const uint4*)(g_Whh2_16 + row * 128 + c * 8);
        *(uint4*)&Wsh[row * WST2 + c * 8] = v;
    }
    for (int idx = tid; idx < 2 * 16 * 17; idx += 512)
        *(uint4*)&ashb[(idx / 17) * WST2 + (idx % 17) * 8] = make_uint4(0, 0, 0, 0);

    float2 bs[4];
#pragma unroll
    for (int nt = 0; nt < 4; nt++) bs[nt] = *(const float2*)&g_b2[chw + nt * 128 + c2];

    float csr[4] = {0,0,0,0}, sum[4] = {0,0,0,0}, sq[4] = {0,0,0,0};
    __syncthreads();

    for (int t = 0; t < T; t++) {
        __half* cur = ashb + (t & 1) * (16 * WST2);
        __half* nxt = ashb + ((t + 1) & 1) * (16 * WST2);

        // fp16 seed fetch (latency hidden under mma)
        float2 sd0[4], sd1[4];
        {
            size_t rowA = ((size_t)(sbase + r4) * T + t) * 512;
            size_t rowB = ((size_t)(sbase + r4 + 8) * T + t) * 512;
#pragma unroll
            for (int nt = 0; nt < 4; nt++) {
                int gcol = chw + nt * 128 + c2;
                unsigned uA = *(const unsigned*)&g_xpre[rowA + gcol];
                unsigned uB = *(const unsigned*)&g_xpre[rowB + gcol];
                sd0[nt] = __half22float2(*(__half2*)&uA);
                sd1[nt] = __half22float2(*(__half2*)&uB);
            }
        }

        float d[4][4];
#pragma unroll
        for (int nt = 0; nt < 4; nt++)
#pragma unroll
            for (int q = 0; q < 4; q++) d[nt][q] = 0.f;

#pragma unroll
        for (int ks = 0; ks < NK2; ks++) {
            int kb = ks * 16;
            const __half* ab = cur + r4 * WST2 + kb + c2;
            unsigned a0 = ldh2(ab);
            unsigned a1 = ldh2(ab + 8 * WST2);
            unsigned a2 = ldh2(ab + 8);
            unsigned a3 = ldh2(ab + 8 * WST2 + 8);
#pragma unroll
            for (int nt = 0; nt < 4; nt++) {
                const __half* bb = Wsh + (chw + nt * 128 + r4) * WST2 + kb + c2;
                mma16816(d[nt][0], d[nt][1], d[nt][2], d[nt][3],
                         a0, a1, a2, a3, ldh2(bb), ldh2(bb + 8));
            }
        }

        float hq[4];
#pragma unroll
        for (int q = 0; q < 4; q++) {
            float si = (q < 2) ? ((q & 1) ? sd0[0].y : sd0[0].x) : ((q & 1) ? sd1[0].y : sd1[0].x);
            float sf = (q < 2) ? ((q & 1) ? sd0[1].y : sd0[1].x) : ((q & 1) ? sd1[1].y : sd1[1].x);
            float sg = (q < 2) ? ((q & 1) ? sd0[2].y : sd0[2].x) : ((q & 1) ? sd1[2].y : sd1[2].x);
            float so = (q < 2) ? ((q & 1) ? sd0[3].y : sd0[3].x) : ((q & 1) ? sd1[3].y : sd1[3].x);
            float zi = d[0][q] + ((q & 1) ? bs[0].y : bs[0].x) + si;
            float zf = d[1][q] + ((q & 1) ? bs[1].y : bs[1].x) + sf;
            float zg = d[2][q] + ((q & 1) ? bs[2].y : bs[2].x) + sg;
            float zo = d[3][q] + ((q & 1) ? bs[3].y : bs[3].x) + so;
            float gi = sigm(zi);
            float gf = sigm(zf);
            float gg = fmaf(2.f, sigm(2.f * zg), -1.f);
            float go = sigm(zo);
            float c = fmaf(gf, csr[q], gi * gg);
            csr[q] = c;
            float h = go * fmaf(2.f, sigm(2.f * c), -1.f);
            hq[q] = h;
            sum[q] += h;
            sq[q] = fmaf(h, h, sq[q]);
        }
        {
            __half2 h01 = __floats2half2_rn(hq[0], hq[1]);
            __half2 h23 = __floats2half2_rn(hq[2], hq[3]);
            *(unsigned*)&nxt[r4 * WST2 + chw + c2]       = *(unsigned*)&h01;
            *(unsigned*)&nxt[(r4 + 8) * WST2 + chw + c2] = *(unsigned*)&h23;
        }
        if (t == T - 1) {
            *(float2*)&g_lasth[(sbase + r4) * H + chw + c2]     = make_float2(hq[0], hq[1]);
            *(float2*)&g_lasth[(sbase + r4 + 8) * H + chw + c2] = make_float2(hq[2], hq[3]);
        }
        __syncthreads();
    }
    *(float2*)&g_ps2[(sbase + r4) * H + chw + c2]     = make_float2(sum[0], sum[1]);
    *(float2*)&g_ps2[(sbase + r4 + 8) * H + chw + c2] = make_float2(sum[2], sum[3]);
    *(float2*)&g_pq2[(sbase + r4) * H + chw + c2]     = make_float2(sq[0], sq[1]);
    *(float2*)&g_pq2[(sbase + r4 + 8) * H + chw + c2] = make_float2(sq[2], sq[3]);
}

// ---------- FC + L2 normalize ----------
__global__ void __launch_bounds__(128)
final_kernel(const float* __restrict__ fcW, const float* __restrict__ fcb, float* __restrict__ out) {
    __shared__ float xn[H];
    __shared__ float emb[H];
    __shared__ float red[128];
    int s = blockIdx.x, j = threadIdx.x;
    int in = s >> 9, b = s & 511;

    float2 bn = g_bn2[in * H + j];
    xn[j] = fmaf(g_lasth[s * H + j], bn.x, bn.y);
    __syncthreads();

    float e = fcb[j];
    const float* wrow = fcW + j * H;
#pragma unroll 4
    for (int k = 0; k < H; k++) e = fmaf(__ldg(&wrow[k]), xn[k], e);
    emb[j] = e;
    red[j] = e * e;
    __syncthreads();
    for (int off = 64; off > 0; off >>= 1) {
        if (j < off) red[j] += red[j + off];
        __syncthreads();
    }
    float norm = sqrtf(red[0]);
    float inv = 1.f / fmaxf(norm, 1e-12f);
    out[((size_t)in * B + b) * H + j] = emb[j] * inv;
}

extern "C" void kernel_launch(void* const* d_in, const int* in_sizes, int n_in,
                              void* d_out, int out_size) {
    const float* a    = (const float*)d_in[0];
    const float* p    = (const float*)d_in[1];
    const float* n    = (const float*)d_in[2];
    const float* Wih1 = (const float*)d_in[3];
    const float* Whh1 = (const float*)d_in[4];
    const float* bih1 = (const float*)d_in[5];
    const float* bhh1 = (const float*)d_in[6];
    const float* g1   = (const float*)d_in[7];
    const float* b1   = (const float*)d_in[8];
    const float* Wih2 = (const float*)d_in[9];
    const float* Whh2 = (const float*)d_in[10];
    const float* bih2 = (const float*)d_in[11];
    const float* bhh2 = (const float*)d_in[12];
    const float* g2   = (const float*)d_in[13];
    const float* b2   = (const float*)d_in[14];
    const float* fcW  = (const float*)d_in[15];
    const float* fcb  = (const float*)d_in[16];
    float* out = (float*)d_out;

    cudaFuncSetAttribute(lstm1_kernel, cudaFuncAttributeMaxDynamicSharedMemorySize, SMEM1_BYTES);
    cudaFuncSetAttribute(lstm2_kernel, cudaFuncAttributeMaxDynamicSharedMemorySize, SMEM2_BYTES);
    cudaFuncSetAttribute(xpre_kernel,  cudaFuncAttributeMaxDynamicSharedMemorySize, XP_SMEM_BYTES);

    float2 *bn1p, *bn2p;
    cudaGetSymbolAddress((void**)&bn1p, g_bn1);
    cudaGetSymbolAddress((void**)&bn2p, g_bn2);
    float *ps1, *pq1, *ps2, *pq2;
    cudaGetSymbolAddress((void**)&ps1, g_ps1);
    cudaGetSymbolAddress((void**)&pq1, g_pq1);
    cudaGetSymbolAddress((void**)&ps2, g_ps2);
    cudaGetSymbolAddress((void**)&pq2, g_pq2);

    prep_kernel<<<128, 256>>>(Wih1, Whh1, bih1, bhh1, Wih2, Whh2, bih2, bhh2);
    lstm1_kernel<<<NBLK2, 512, SMEM1_BYTES>>>(a, p, n);
    bn_reduce_kernel<<<3 * H, 128>>>(ps1, pq1, g1, b1, bn1p);
    xpre_kernel<<<(S * T) / 128, 512, XP_SMEM_BYTES>>>();
    lstm2_kernel<<<NBLK2, 512, SMEM2_BYTES>>>();
    bn_reduce_kernel<<<3 * H, 128>>>(ps2, pq2, g2, b2, bn2p);
    final_kernel<<<S, 128>>>(fcW, fcb, out);
}